// round 1
// baseline (speedup 1.0000x reference)
#include <cuda_runtime.h>
#include <cuda_bf16.h>
#include <math.h>

#define N_NODES 16384
#define NPG 512
#define B 32
#define E_EDGES 262144
#define H 64
#define HEADS 8
#define DH 8

// ---------------- scratch (device globals; allocation-free) ----------------
__device__ float g_h[N_NODES * H];      // x @ w_gat
__device__ float g_es[N_NODES];         // h @ att_src
__device__ float g_ed[N_NODES];         // h @ att_dst
__device__ float g_m[N_NODES];          // segment max
__device__ float g_s[N_NODES];          // segment sum of exp
__device__ float g_eedge[E_EDGES];      // per-edge leaky score
__device__ float g_acc[N_NODES * H];    // sum p * h[src]
__device__ float g_x1[N_NODES * H];     // LN1 output
__device__ float g_q[N_NODES * H];
__device__ float g_k[N_NODES * H];
__device__ float g_v[N_NODES * H];
__device__ float g_ao[N_NODES * H];     // attention output (pre-wo)

__device__ __forceinline__ float leaky02(float e) {
    return e > 0.0f ? e : 0.2f * e;
}

__device__ __forceinline__ void atomicMaxFloat(float* addr, float value) {
    // ordered-int trick, valid for all finite floats
    if (value >= 0.0f) {
        atomicMax((int*)addr, __float_as_int(value));
    } else {
        atomicMin((unsigned int*)addr, __float_as_uint(value));
    }
}

// ---------------- K1: h = x @ w_gat ; es = h@att_src ; ed = h@att_dst ------
__global__ void k1_gat_proj(const float* __restrict__ x, const float* __restrict__ w,
                            const float* __restrict__ asrc, const float* __restrict__ adst) {
    __shared__ float sw[64 * 64];
    __shared__ float sx[4][64];
    __shared__ float s_es[4], s_ed[4];
    int t = threadIdx.x;                 // 256 threads
    for (int i = t; i < 4096; i += 256) sw[i] = w[i];
    int row0 = blockIdx.x * 4;
    sx[t >> 6][t & 63] = x[row0 * 64 + t];
    if (t < 4) { s_es[t] = 0.0f; s_ed[t] = 0.0f; }
    __syncthreads();
    int r = t >> 6, j = t & 63;
    float acc = 0.0f;
#pragma unroll
    for (int kk = 0; kk < 64; kk++) acc += sx[r][kk] * sw[kk * 64 + j];
    int node = row0 + r;
    g_h[node * 64 + j] = acc;
    atomicAdd(&s_es[r], acc * asrc[j]);
    atomicAdd(&s_ed[r], acc * adst[j]);
    __syncthreads();
    if (t < 4) { g_es[row0 + t] = s_es[t]; g_ed[row0 + t] = s_ed[t]; }
}

// ---------------- K2a: init m with self-loop score -------------------------
__global__ void k2a_init_m() {
    int i = blockIdx.x * blockDim.x + threadIdx.x;
    if (i >= N_NODES) return;
    g_m[i] = leaky02(g_es[i] + g_ed[i]);
}

// ---------------- K2b: per-edge score + segment max ------------------------
__global__ void k2b_edge_max(const int* __restrict__ ei) {
    int k = blockIdx.x * blockDim.x + threadIdx.x;
    if (k >= E_EDGES) return;
    int src = ei[k];
    int dst = ei[E_EDGES + k];
    float e = leaky02(g_es[src] + g_ed[dst]);
    g_eedge[k] = e;
    atomicMaxFloat(&g_m[dst], e);
}

// ---------------- K3a: init acc,s with self-loop contribution --------------
__global__ void k3a_init_acc() {
    int idx = blockIdx.x * blockDim.x + threadIdx.x;   // N*64
    int node = idx >> 6, j = idx & 63;
    float e = leaky02(g_es[node] + g_ed[node]);
    float p = __expf(e - g_m[node]);
    g_acc[idx] = p * g_h[idx];
    if (j == 0) g_s[node] = p;
}

// ---------------- K3b: fused exp-sum + weighted aggregation ----------------
__global__ void k3b_edge_agg(const int* __restrict__ ei) {
    int gtid = blockIdx.x * blockDim.x + threadIdx.x;
    int edge = gtid >> 4;       // 16 lanes per edge
    int lane = gtid & 15;
    if (edge >= E_EDGES) return;
    int src = ei[edge];
    int dst = ei[E_EDGES + edge];
    float p = __expf(g_eedge[edge] - g_m[dst]);
    if (lane == 0) atomicAdd(&g_s[dst], p);
    float4 hv = *(const float4*)&g_h[src * 64 + lane * 4];
    float4 pv = make_float4(p * hv.x, p * hv.y, p * hv.z, p * hv.w);
#if __CUDA_ARCH__ >= 900
    atomicAdd((float4*)&g_acc[dst * 64 + lane * 4], pv);
#else
    atomicAdd(&g_acc[dst * 64 + lane * 4 + 0], pv.x);
    atomicAdd(&g_acc[dst * 64 + lane * 4 + 1], pv.y);
    atomicAdd(&g_acc[dst * 64 + lane * 4 + 2], pv.z);
    atomicAdd(&g_acc[dst * 64 + lane * 4 + 3], pv.w);
#endif
}

// ---------------- K4: x1 = LN(x + relu(gat + b_gat)) -----------------------
__global__ void k4_ln1(const float* __restrict__ x, const float* __restrict__ b_gat,
                       const float* __restrict__ g1, const float* __restrict__ b1) {
    int warp = (blockIdx.x * blockDim.x + threadIdx.x) >> 5;
    int lane = threadIdx.x & 31;
    if (warp >= N_NODES) return;
    int node = warp;
    float inv_s = 1.0f / (g_s[node] + 1e-16f);
    float v[2];
    float sum = 0.0f, sumsq = 0.0f;
#pragma unroll
    for (int u = 0; u < 2; u++) {
        int j = lane + u * 32;
        float go = g_acc[node * 64 + j] * inv_s + b_gat[j];
        go = go > 0.0f ? go : 0.0f;
        float val = x[node * 64 + j] + go;
        v[u] = val; sum += val; sumsq += val * val;
    }
#pragma unroll
    for (int o = 16; o; o >>= 1) {
        sum   += __shfl_xor_sync(0xffffffffu, sum, o);
        sumsq += __shfl_xor_sync(0xffffffffu, sumsq, o);
    }
    float mu = sum * (1.0f / 64.0f);
    float var = sumsq * (1.0f / 64.0f) - mu * mu;
    float rstd = rsqrtf(var + 1e-5f);
#pragma unroll
    for (int u = 0; u < 2; u++) {
        int j = lane + u * 32;
        g_x1[node * 64 + j] = (v[u] - mu) * rstd * g1[j] + b1[j];
    }
}

// ---------------- K5: generic 64x64 projection from g_x1 -------------------
__global__ void gemm64(const float* __restrict__ w, const float* __restrict__ bias, int sel) {
    __shared__ float sw[64 * 64];
    __shared__ float sx[4][64];
    int t = threadIdx.x;
    for (int i = t; i < 4096; i += 256) sw[i] = w[i];
    int row0 = blockIdx.x * 4;
    sx[t >> 6][t & 63] = g_x1[row0 * 64 + t];
    __syncthreads();
    int r = t >> 6, j = t & 63;
    float a = 0.0f;
#pragma unroll
    for (int kk = 0; kk < 64; kk++) a += sx[r][kk] * sw[kk * 64 + j];
    a += bias[j];
    float* outp = (sel == 0) ? g_q : (sel == 1) ? g_k : g_v;
    outp[(row0 + r) * 64 + j] = a;
}

// ---------------- K6: per-(graph,head) dense attention ---------------------
__global__ void k6_attn() {
    // blockIdx.x = b*8 + h ; 256 threads (8 warps)
    __shared__ float sKt[DH][NPG];   // d-major: conflict-free strided key access
    __shared__ float sVt[DH][NPG];
    int bh = blockIdx.x;
    int b = bh >> 3, h = bh & 7;
    int base = b * NPG;
    int t = threadIdx.x;
    for (int i = t; i < NPG * DH; i += 256) {
        int n = i >> 3, d = i & 7;
        sKt[d][n] = g_k[(base + n) * 64 + h * DH + d];
        sVt[d][n] = g_v[(base + n) * 64 + h * DH + d];
    }
    __syncthreads();
    int warp = t >> 5, lane = t & 31;
    const float scale = 0.3535533905932738f;   // 1/sqrt(8)
    for (int q = warp; q < NPG; q += 8) {
        float qr[DH];
#pragma unroll
        for (int d = 0; d < DH; d++) qr[d] = g_q[(base + q) * 64 + h * DH + d] * scale;
        float sc[16];
        float mx = -1e30f;
#pragma unroll
        for (int kk = 0; kk < 16; kk++) {
            int key = lane + kk * 32;
            float dot = 0.0f;
#pragma unroll
            for (int d = 0; d < DH; d++) dot += qr[d] * sKt[d][key];
            sc[kk] = dot;
            mx = fmaxf(mx, dot);
        }
#pragma unroll
        for (int o = 16; o; o >>= 1) mx = fmaxf(mx, __shfl_xor_sync(0xffffffffu, mx, o));
        float ssum = 0.0f;
        float acc[DH] = {0, 0, 0, 0, 0, 0, 0, 0};
#pragma unroll
        for (int kk = 0; kk < 16; kk++) {
            int key = lane + kk * 32;
            float p = __expf(sc[kk] - mx);
            ssum += p;
#pragma unroll
            for (int d = 0; d < DH; d++) acc[d] += p * sVt[d][key];
        }
#pragma unroll
        for (int o = 16; o; o >>= 1) {
            ssum += __shfl_xor_sync(0xffffffffu, ssum, o);
#pragma unroll
            for (int d = 0; d < DH; d++) acc[d] += __shfl_xor_sync(0xffffffffu, acc[d], o);
        }
        float inv = 1.0f / ssum;
#pragma unroll
        for (int d = 0; d < DH; d++)
            if (lane == d) g_ao[(base + q) * 64 + h * DH + d] = acc[d] * inv;
    }
}

// ---------------- K7: out = LN(x1 + relu(ao @ wo + bo)) --------------------
__global__ void k7_out(const float* __restrict__ wo, const float* __restrict__ bo,
                       const float* __restrict__ g2, const float* __restrict__ b2,
                       float* __restrict__ out) {
    __shared__ float sw[64 * 64];
    __shared__ float sx[4][64];
    __shared__ float red[4][2];
    int t = threadIdx.x;
    for (int i = t; i < 4096; i += 256) sw[i] = wo[i];
    int row0 = blockIdx.x * 4;
    sx[t >> 6][t & 63] = g_ao[row0 * 64 + t];
    if (t < 8) ((float*)red)[t] = 0.0f;
    __syncthreads();
    int r = t >> 6, j = t & 63;
    float a = 0.0f;
#pragma unroll
    for (int kk = 0; kk < 64; kk++) a += sx[r][kk] * sw[kk * 64 + j];
    a += bo[j];
    a = a > 0.0f ? a : 0.0f;
    float val = g_x1[(row0 + r) * 64 + j] + a;
    atomicAdd(&red[r][0], val);
    atomicAdd(&red[r][1], val * val);
    __syncthreads();
    float mu = red[r][0] * (1.0f / 64.0f);
    float var = red[r][1] * (1.0f / 64.0f) - mu * mu;
    float rstd = rsqrtf(var + 1e-5f);
    out[(row0 + r) * 64 + j] = (val - mu) * rstd * g2[j] + b2[j];
}

// ---------------- launch ----------------------------------------------------
extern "C" void kernel_launch(void* const* d_in, const int* in_sizes, int n_in,
                              void* d_out, int out_size) {
    const float* x       = (const float*)d_in[0];
    const float* w_gat   = (const float*)d_in[1];
    const float* att_src = (const float*)d_in[2];
    const float* att_dst = (const float*)d_in[3];
    const float* b_gat   = (const float*)d_in[4];
    const float* g1      = (const float*)d_in[5];
    const float* b1      = (const float*)d_in[6];
    const float* wq      = (const float*)d_in[7];
    const float* bq      = (const float*)d_in[8];
    const float* wk      = (const float*)d_in[9];
    const float* bk      = (const float*)d_in[10];
    const float* wv      = (const float*)d_in[11];
    const float* bv      = (const float*)d_in[12];
    const float* wo      = (const float*)d_in[13];
    const float* bo      = (const float*)d_in[14];
    const float* g2      = (const float*)d_in[15];
    const float* b2      = (const float*)d_in[16];
    const int*   ei      = (const int*)d_in[17];
    float* out = (float*)d_out;

    k1_gat_proj<<<N_NODES / 4, 256>>>(x, w_gat, att_src, att_dst);
    k2a_init_m<<<N_NODES / 256, 256>>>();
    k2b_edge_max<<<E_EDGES / 256, 256>>>(ei);
    k3a_init_acc<<<N_NODES * 64 / 256, 256>>>();
    k3b_edge_agg<<<(E_EDGES * 16) / 256, 256>>>(ei);
    k4_ln1<<<N_NODES * 32 / 256, 256>>>(x, b_gat, g1, b1);
    gemm64<<<N_NODES / 4, 256>>>(wq, bq, 0);
    gemm64<<<N_NODES / 4, 256>>>(wk, bk, 1);
    gemm64<<<N_NODES / 4, 256>>>(wv, bv, 2);
    k6_attn<<<B * HEADS, 256>>>();
    k7_out<<<N_NODES / 4, 256>>>(wo, bo, g2, b2, out);
}

// round 2
// speedup vs baseline: 1.4836x; 1.4836x over previous
#include <cuda_runtime.h>
#include <cuda_bf16.h>
#include <math.h>

#define N_NODES 16384
#define NPG 512
#define B 32
#define E_EDGES 262144
#define H 64
#define HEADS 8
#define DH 8

typedef unsigned long long u64;

// ---------------- scratch (device globals; allocation-free) ----------------
__device__ float g_h[N_NODES * H];      // x @ w_gat
__device__ float g_es[N_NODES];         // h @ att_src
__device__ float g_ed[N_NODES];         // h @ att_dst
__device__ float g_m[N_NODES];          // segment max
__device__ float g_s[N_NODES];          // segment sum of exp
__device__ float g_eedge[E_EDGES];      // per-edge leaky score
__device__ float g_acc[N_NODES * H];    // sum p * h[src]
__device__ float g_x1[N_NODES * H];     // LN1 output
__device__ float g_q[N_NODES * H];
__device__ float g_k[N_NODES * H];
__device__ float g_v[N_NODES * H];
__device__ float g_ao[N_NODES * H];     // attention output (pre-wo)

__device__ __forceinline__ float leaky02(float e) {
    return e > 0.0f ? e : 0.2f * e;
}

__device__ __forceinline__ void atomicMaxFloat(float* addr, float value) {
    if (value >= 0.0f) {
        atomicMax((int*)addr, __float_as_int(value));
    } else {
        atomicMin((unsigned int*)addr, __float_as_uint(value));
    }
}

// ---------------- packed fp32x2 helpers (sm_103a FFMA2) --------------------
__device__ __forceinline__ u64 f2pack(float lo, float hi) {
    u64 r; asm("mov.b64 %0, {%1, %2};" : "=l"(r) : "f"(lo), "f"(hi)); return r;
}
__device__ __forceinline__ void f2unpack(u64 v, float& lo, float& hi) {
    asm("mov.b64 {%0, %1}, %2;" : "=f"(lo), "=f"(hi) : "l"(v));
}
__device__ __forceinline__ u64 fma2(u64 a, u64 b, u64 c) {
    u64 d; asm("fma.rn.f32x2 %0, %1, %2, %3;" : "=l"(d) : "l"(a), "l"(b), "l"(c)); return d;
}
__device__ __forceinline__ u64 mul2(u64 a, u64 b) {
    u64 d; asm("mul.rn.f32x2 %0, %1, %2;" : "=l"(d) : "l"(a), "l"(b)); return d;
}
__device__ __forceinline__ u64 add2(u64 a, u64 b) {
    u64 d; asm("add.rn.f32x2 %0, %1, %2;" : "=l"(d) : "l"(a), "l"(b)); return d;
}

// ---------------- K1: h = x @ w_gat ; es = h@att_src ; ed = h@att_dst ------
// 16 rows per block, float4 accumulation.
__global__ void k1_gat_proj(const float* __restrict__ x, const float* __restrict__ w,
                            const float* __restrict__ asrc, const float* __restrict__ adst) {
    __shared__ float sw[4096];
    __shared__ float sx[16][64];
    __shared__ float s_es[16], s_ed[16];
    int t = threadIdx.x;                 // 256 threads
    for (int i = t; i < 4096; i += 256) sw[i] = w[i];
    int row0 = blockIdx.x * 16;
    for (int i = t; i < 1024; i += 256) sx[i >> 6][i & 63] = x[row0 * 64 + i];
    if (t < 16) { s_es[t] = 0.0f; s_ed[t] = 0.0f; }
    __syncthreads();
    int r = t >> 4, j4 = t & 15;
    const float4* sw4 = (const float4*)sw;
    float4 a = make_float4(0.f, 0.f, 0.f, 0.f);
#pragma unroll
    for (int kk = 0; kk < 64; kk++) {
        float xv = sx[r][kk];
        float4 wv = sw4[kk * 16 + j4];
        a.x = fmaf(xv, wv.x, a.x);
        a.y = fmaf(xv, wv.y, a.y);
        a.z = fmaf(xv, wv.z, a.z);
        a.w = fmaf(xv, wv.w, a.w);
    }
    *(float4*)&g_h[(row0 + r) * 64 + j4 * 4] = a;
    float4 av = *(const float4*)&asrc[j4 * 4];
    float4 dv = *(const float4*)&adst[j4 * 4];
    atomicAdd(&s_es[r], a.x * av.x + a.y * av.y + a.z * av.z + a.w * av.w);
    atomicAdd(&s_ed[r], a.x * dv.x + a.y * dv.y + a.z * dv.z + a.w * dv.w);
    __syncthreads();
    if (t < 16) { g_es[row0 + t] = s_es[t]; g_ed[row0 + t] = s_ed[t]; }
}

// ---------------- K2a: init m with self-loop score -------------------------
__global__ void k2a_init_m() {
    int i = blockIdx.x * blockDim.x + threadIdx.x;
    if (i >= N_NODES) return;
    g_m[i] = leaky02(g_es[i] + g_ed[i]);
}

// ---------------- K2b: per-edge score + segment max ------------------------
__global__ void k2b_edge_max(const int* __restrict__ ei) {
    int k = blockIdx.x * blockDim.x + threadIdx.x;
    if (k >= E_EDGES) return;
    int src = ei[k];
    int dst = ei[E_EDGES + k];
    float e = leaky02(g_es[src] + g_ed[dst]);
    g_eedge[k] = e;
    atomicMaxFloat(&g_m[dst], e);
}

// ---------------- K3a: init acc,s with self-loop contribution --------------
__global__ void k3a_init_acc() {
    int idx = blockIdx.x * blockDim.x + threadIdx.x;   // N*16
    int node = idx >> 4, j4 = idx & 15;
    float e = leaky02(g_es[node] + g_ed[node]);
    float p = __expf(e - g_m[node]);
    float4 hv = *(const float4*)&g_h[node * 64 + j4 * 4];
    *(float4*)&g_acc[node * 64 + j4 * 4] = make_float4(p * hv.x, p * hv.y, p * hv.z, p * hv.w);
    if (j4 == 0) g_s[node] = p;
}

// ---------------- K3b: fused exp-sum + weighted aggregation ----------------
__global__ void k3b_edge_agg(const int* __restrict__ ei) {
    int gtid = blockIdx.x * blockDim.x + threadIdx.x;
    int edge = gtid >> 4;       // 16 lanes per edge
    int lane = gtid & 15;
    if (edge >= E_EDGES) return;
    int src = ei[edge];
    int dst = ei[E_EDGES + edge];
    float p = __expf(g_eedge[edge] - g_m[dst]);
    if (lane == 0) atomicAdd(&g_s[dst], p);
    float4 hv = *(const float4*)&g_h[src * 64 + lane * 4];
    float4 pv = make_float4(p * hv.x, p * hv.y, p * hv.z, p * hv.w);
    atomicAdd((float4*)&g_acc[dst * 64 + lane * 4], pv);
}

// ---------------- K4: x1 = LN(x + relu(gat + b_gat)) -----------------------
__global__ void k4_ln1(const float* __restrict__ x, const float* __restrict__ b_gat,
                       const float* __restrict__ g1, const float* __restrict__ b1) {
    int warp = (blockIdx.x * blockDim.x + threadIdx.x) >> 5;
    int lane = threadIdx.x & 31;
    if (warp >= N_NODES) return;
    int node = warp;
    float inv_s = 1.0f / (g_s[node] + 1e-16f);
    float v[2];
    float sum = 0.0f, sumsq = 0.0f;
#pragma unroll
    for (int u = 0; u < 2; u++) {
        int j = lane + u * 32;
        float go = g_acc[node * 64 + j] * inv_s + b_gat[j];
        go = go > 0.0f ? go : 0.0f;
        float val = x[node * 64 + j] + go;
        v[u] = val; sum += val; sumsq += val * val;
    }
#pragma unroll
    for (int o = 16; o; o >>= 1) {
        sum   += __shfl_xor_sync(0xffffffffu, sum, o);
        sumsq += __shfl_xor_sync(0xffffffffu, sumsq, o);
    }
    float mu = sum * (1.0f / 64.0f);
    float var = sumsq * (1.0f / 64.0f) - mu * mu;
    float rstd = rsqrtf(var + 1e-5f);
#pragma unroll
    for (int u = 0; u < 2; u++) {
        int j = lane + u * 32;
        g_x1[node * 64 + j] = (v[u] - mu) * rstd * g1[j] + b1[j];
    }
}

// ---------------- K5: 64x64 projection from g_x1, 16 rows/block ------------
__global__ void gemm64(const float* __restrict__ w, const float* __restrict__ bias, int sel) {
    __shared__ float sw[4096];
    __shared__ float sx[16][64];
    int t = threadIdx.x;
    for (int i = t; i < 4096; i += 256) sw[i] = w[i];
    int row0 = blockIdx.x * 16;
    for (int i = t; i < 1024; i += 256) sx[i >> 6][i & 63] = g_x1[row0 * 64 + i];
    __syncthreads();
    int r = t >> 4, j4 = t & 15;
    const float4* sw4 = (const float4*)sw;
    float4 a = make_float4(0.f, 0.f, 0.f, 0.f);
#pragma unroll
    for (int kk = 0; kk < 64; kk++) {
        float xv = sx[r][kk];
        float4 wv = sw4[kk * 16 + j4];
        a.x = fmaf(xv, wv.x, a.x);
        a.y = fmaf(xv, wv.y, a.y);
        a.z = fmaf(xv, wv.z, a.z);
        a.w = fmaf(xv, wv.w, a.w);
    }
    float4 bv = *(const float4*)&bias[j4 * 4];
    a.x += bv.x; a.y += bv.y; a.z += bv.z; a.w += bv.w;
    float* outp = (sel == 0) ? g_q : (sel == 1) ? g_k : g_v;
    *(float4*)&outp[(row0 + r) * 64 + j4 * 4] = a;
}

// ---------------- K6: dense attention, one lane = one query ----------------
// grid = B*HEADS*2 blocks, 256 threads. Each block: (b,h) pair, half of the
// 512 queries. Keys/values in smem, broadcast reads, online softmax over
// 32-key tiles, packed f32x2 FMA throughout. No cross-lane reductions.
#define KTILE 32
__global__ void __launch_bounds__(256, 2) k6_attn() {
    __shared__ float sKt[8][512];       // d-major: pair-of-keys f32x2 loads
    __shared__ float4 sV4[512][2];      // key-major 32B rows
    int bh = blockIdx.x >> 1;
    int half = blockIdx.x & 1;
    int b = bh >> 3, h = bh & 7;
    int base = b * NPG;
    int t = threadIdx.x;
    for (int i = t; i < 4096; i += 256) {
        int n = i >> 3, d = i & 7;
        sKt[d][n] = g_k[(base + n) * 64 + h * DH + d];
    }
    for (int i = t; i < 1024; i += 256) {
        int n = i >> 1, p = i & 1;
        sV4[n][p] = *(const float4*)&g_v[(base + n) * 64 + h * DH + p * 4];
    }
    __syncthreads();

    int q = half * 256 + t;
    const float scale = 0.3535533905932738f;   // 1/sqrt(8)
    float4 qa = *(const float4*)&g_q[(base + q) * 64 + h * DH];
    float4 qb = *(const float4*)&g_q[(base + q) * 64 + h * DH + 4];
    u64 qq[8];
    qq[0] = f2pack(qa.x * scale, qa.x * scale);
    qq[1] = f2pack(qa.y * scale, qa.y * scale);
    qq[2] = f2pack(qa.z * scale, qa.z * scale);
    qq[3] = f2pack(qa.w * scale, qa.w * scale);
    qq[4] = f2pack(qb.x * scale, qb.x * scale);
    qq[5] = f2pack(qb.y * scale, qb.y * scale);
    qq[6] = f2pack(qb.z * scale, qb.z * scale);
    qq[7] = f2pack(qb.w * scale, qb.w * scale);

    float m = -1e30f;
    u64 sum2 = 0ULL;                     // packed (0,0)
    u64 acc2[4] = {0ULL, 0ULL, 0ULL, 0ULL};

#pragma unroll 1
    for (int tile = 0; tile < NPG / KTILE; tile++) {
        u64 sc[KTILE / 2];
        float tm = -1e30f;
#pragma unroll
        for (int j = 0; j < KTILE / 2; j++) {
            u64 s = 0ULL;
#pragma unroll
            for (int d = 0; d < 8; d++) {
                u64 kv = *(const u64*)&sKt[d][tile * KTILE + 2 * j];
                s = fma2(qq[d], kv, s);
            }
            sc[j] = s;
            float s0, s1; f2unpack(s, s0, s1);
            tm = fmaxf(tm, fmaxf(s0, s1));
        }
        float mn = fmaxf(m, tm);
        float rsc = __expf(m - mn);
        m = mn;
        u64 rr = f2pack(rsc, rsc);
        sum2 = mul2(sum2, rr);
#pragma unroll
        for (int p = 0; p < 4; p++) acc2[p] = mul2(acc2[p], rr);
#pragma unroll
        for (int j = 0; j < KTILE / 2; j++) {
            float s0, s1; f2unpack(sc[j], s0, s1);
            float p0 = __expf(s0 - m);
            float p1 = __expf(s1 - m);
            sum2 = add2(sum2, f2pack(p0, p1));
            u64 pp0 = f2pack(p0, p0);
            u64 pp1 = f2pack(p1, p1);
            int k0 = tile * KTILE + 2 * j;
            const u64* v0 = (const u64*)&sV4[k0][0];
            const u64* v1 = (const u64*)&sV4[k0 + 1][0];
#pragma unroll
            for (int p = 0; p < 4; p++) acc2[p] = fma2(pp0, v0[p], acc2[p]);
#pragma unroll
            for (int p = 0; p < 4; p++) acc2[p] = fma2(pp1, v1[p], acc2[p]);
        }
    }
    float sl, sh; f2unpack(sum2, sl, sh);
    float inv = 1.0f / (sl + sh);
    float o[8];
#pragma unroll
    for (int p = 0; p < 4; p++) f2unpack(acc2[p], o[2 * p], o[2 * p + 1]);
    float4 oa = make_float4(o[0] * inv, o[1] * inv, o[2] * inv, o[3] * inv);
    float4 ob = make_float4(o[4] * inv, o[5] * inv, o[6] * inv, o[7] * inv);
    *(float4*)&g_ao[(base + q) * 64 + h * DH] = oa;
    *(float4*)&g_ao[(base + q) * 64 + h * DH + 4] = ob;
}

// ---------------- K7: out = LN(x1 + relu(ao @ wo + bo)) --------------------
__global__ void k7_out(const float* __restrict__ wo, const float* __restrict__ bo,
                       const float* __restrict__ g2, const float* __restrict__ b2,
                       float* __restrict__ out) {
    __shared__ float sw[4096];
    __shared__ float sx[16][64];
    __shared__ float red[16][2];
    int t = threadIdx.x;
    for (int i = t; i < 4096; i += 256) sw[i] = wo[i];
    int row0 = blockIdx.x * 16;
    for (int i = t; i < 1024; i += 256) sx[i >> 6][i & 63] = g_ao[row0 * 64 + i];
    if (t < 32) ((float*)red)[t] = 0.0f;
    __syncthreads();
    int r = t >> 4, j4 = t & 15;
    const float4* sw4 = (const float4*)sw;
    float4 a = make_float4(0.f, 0.f, 0.f, 0.f);
#pragma unroll
    for (int kk = 0; kk < 64; kk++) {
        float xv = sx[r][kk];
        float4 wv = sw4[kk * 16 + j4];
        a.x = fmaf(xv, wv.x, a.x);
        a.y = fmaf(xv, wv.y, a.y);
        a.z = fmaf(xv, wv.z, a.z);
        a.w = fmaf(xv, wv.w, a.w);
    }
    float4 bv = *(const float4*)&bo[j4 * 4];
    a.x = fmaxf(a.x + bv.x, 0.0f);
    a.y = fmaxf(a.y + bv.y, 0.0f);
    a.z = fmaxf(a.z + bv.z, 0.0f);
    a.w = fmaxf(a.w + bv.w, 0.0f);
    float4 x1v = *(const float4*)&g_x1[(row0 + r) * 64 + j4 * 4];
    float4 val = make_float4(x1v.x + a.x, x1v.y + a.y, x1v.z + a.z, x1v.w + a.w);
    float vsum = val.x + val.y + val.z + val.w;
    float vsq  = val.x * val.x + val.y * val.y + val.z * val.z + val.w * val.w;
    atomicAdd(&red[r][0], vsum);
    atomicAdd(&red[r][1], vsq);
    __syncthreads();
    float mu = red[r][0] * (1.0f / 64.0f);
    float var = red[r][1] * (1.0f / 64.0f) - mu * mu;
    float rstd = rsqrtf(var + 1e-5f);
    float4 gv = *(const float4*)&g2[j4 * 4];
    float4 bb = *(const float4*)&b2[j4 * 4];
    float4 ov;
    ov.x = (val.x - mu) * rstd * gv.x + bb.x;
    ov.y = (val.y - mu) * rstd * gv.y + bb.y;
    ov.z = (val.z - mu) * rstd * gv.z + bb.z;
    ov.w = (val.w - mu) * rstd * gv.w + bb.w;
    *(float4*)&out[(row0 + r) * 64 + j4 * 4] = ov;
}

// ---------------- launch ----------------------------------------------------
extern "C" void kernel_launch(void* const* d_in, const int* in_sizes, int n_in,
                              void* d_out, int out_size) {
    const float* x       = (const float*)d_in[0];
    const float* w_gat   = (const float*)d_in[1];
    const float* att_src = (const float*)d_in[2];
    const float* att_dst = (const float*)d_in[3];
    const float* b_gat   = (const float*)d_in[4];
    const float* g1      = (const float*)d_in[5];
    const float* b1      = (const float*)d_in[6];
    const float* wq      = (const float*)d_in[7];
    const float* bq      = (const float*)d_in[8];
    const float* wk      = (const float*)d_in[9];
    const float* bk      = (const float*)d_in[10];
    const float* wv      = (const float*)d_in[11];
    const float* bv      = (const float*)d_in[12];
    const float* wo      = (const float*)d_in[13];
    const float* bo      = (const float*)d_in[14];
    const float* g2      = (const float*)d_in[15];
    const float* b2      = (const float*)d_in[16];
    const int*   ei      = (const int*)d_in[17];
    float* out = (float*)d_out;

    k1_gat_proj<<<N_NODES / 16, 256>>>(x, w_gat, att_src, att_dst);
    k2a_init_m<<<N_NODES / 256, 256>>>();
    k2b_edge_max<<<E_EDGES / 256, 256>>>(ei);
    k3a_init_acc<<<N_NODES * 16 / 256, 256>>>();
    k3b_edge_agg<<<(E_EDGES * 16) / 256, 256>>>(ei);
    k4_ln1<<<N_NODES * 32 / 256, 256>>>(x, b_gat, g1, b1);
    gemm64<<<N_NODES / 16, 256>>>(wq, bq, 0);
    gemm64<<<N_NODES / 16, 256>>>(wk, bk, 1);
    gemm64<<<N_NODES / 16, 256>>>(wv, bv, 2);
    k6_attn<<<B * HEADS * 2, 256>>>();
    k7_out<<<N_NODES / 16, 256>>>(wo, bo, g2, b2, out);
}

// round 3
// speedup vs baseline: 2.3025x; 1.5519x over previous
#include <cuda_runtime.h>
#include <cuda_bf16.h>
#include <math.h>

#define N_NODES 16384
#define NPG 512
#define B 32
#define E_EDGES 262144
#define H 64
#define HEADS 8
#define DH 8

typedef unsigned long long u64;

// ---------------- scratch (device globals; allocation-free) ----------------
__device__ float g_h[N_NODES * H];      // x @ w_gat
__device__ float g_es[N_NODES];         // h @ att_src
__device__ float g_ed[N_NODES];         // h @ att_dst
__device__ float g_x1[N_NODES * H];     // LN1 output
__device__ float g_q[N_NODES * H];
__device__ float g_k[N_NODES * H];
__device__ float g_v[N_NODES * H];
__device__ float g_ao[N_NODES * H];     // attention output (pre-wo)
__device__ int   g_cnt[N_NODES];        // in-degree
__device__ int   g_off[N_NODES];        // CSR row offsets (exclusive scan)
__device__ int   g_cur[N_NODES];        // scatter cursors
__device__ int   g_csrc[E_EDGES];       // CSR src indices grouped by dst

__device__ __forceinline__ float leaky02(float e) {
    return e > 0.0f ? e : 0.2f * e;
}

// ---------------- packed fp32x2 helpers (sm_103a FFMA2) --------------------
__device__ __forceinline__ u64 f2pack(float lo, float hi) {
    u64 r; asm("mov.b64 %0, {%1, %2};" : "=l"(r) : "f"(lo), "f"(hi)); return r;
}
__device__ __forceinline__ void f2unpack(u64 v, float& lo, float& hi) {
    asm("mov.b64 {%0, %1}, %2;" : "=f"(lo), "=f"(hi) : "l"(v));
}
__device__ __forceinline__ u64 fma2(u64 a, u64 b, u64 c) {
    u64 d; asm("fma.rn.f32x2 %0, %1, %2, %3;" : "=l"(d) : "l"(a), "l"(b), "l"(c)); return d;
}
__device__ __forceinline__ u64 mul2(u64 a, u64 b) {
    u64 d; asm("mul.rn.f32x2 %0, %1, %2;" : "=l"(d) : "l"(a), "l"(b)); return d;
}
__device__ __forceinline__ u64 add2(u64 a, u64 b) {
    u64 d; asm("add.rn.f32x2 %0, %1, %2;" : "=l"(d) : "l"(a), "l"(b)); return d;
}

// ---------------- CSR build ------------------------------------------------
__global__ void kc_zero() {
    int i = blockIdx.x * blockDim.x + threadIdx.x;
    if (i < N_NODES) g_cnt[i] = 0;
}

__global__ void kc_count(const int* __restrict__ ei) {
    int k = blockIdx.x * blockDim.x + threadIdx.x;
    if (k >= E_EDGES) return;
    atomicAdd(&g_cnt[ei[E_EDGES + k]], 1);
}

// single block, 1024 threads, 16 values per thread
__global__ void kc_scan() {
    __shared__ int swarp[32];
    int t = threadIdx.x;
    int vals[16];
    int base = t * 16;
    int sum = 0;
#pragma unroll
    for (int i = 0; i < 16; i++) { vals[i] = g_cnt[base + i]; sum += vals[i]; }
    int lane = t & 31, w = t >> 5;
    // inclusive warp scan of sum
    int incl = sum;
#pragma unroll
    for (int o = 1; o < 32; o <<= 1) {
        int v = __shfl_up_sync(0xffffffffu, incl, o);
        if (lane >= o) incl += v;
    }
    if (lane == 31) swarp[w] = incl;
    __syncthreads();
    if (w == 0) {
        int v = swarp[lane];
        int iv = v;
#pragma unroll
        for (int o = 1; o < 32; o <<= 1) {
            int u = __shfl_up_sync(0xffffffffu, iv, o);
            if (lane >= o) iv += u;
        }
        swarp[lane] = iv - v;   // exclusive
    }
    __syncthreads();
    int run = incl - sum + swarp[w];
#pragma unroll
    for (int i = 0; i < 16; i++) {
        g_off[base + i] = run;
        g_cur[base + i] = run;
        run += vals[i];
    }
}

__global__ void kc_scatter(const int* __restrict__ ei) {
    int k = blockIdx.x * blockDim.x + threadIdx.x;
    if (k >= E_EDGES) return;
    int src = ei[k];
    int dst = ei[E_EDGES + k];
    int pos = atomicAdd(&g_cur[dst], 1);
    g_csrc[pos] = src;
}

// ---------------- K1: h = x @ w_gat ; es = h@att_src ; ed = h@att_dst ------
__global__ void k1_gat_proj(const float* __restrict__ x, const float* __restrict__ w,
                            const float* __restrict__ asrc, const float* __restrict__ adst) {
    __shared__ float sw[4096];
    __shared__ float sx[16][64];
    __shared__ float s_es[16], s_ed[16];
    int t = threadIdx.x;                 // 256 threads
    for (int i = t; i < 4096; i += 256) sw[i] = w[i];
    int row0 = blockIdx.x * 16;
    for (int i = t; i < 1024; i += 256) sx[i >> 6][i & 63] = x[row0 * 64 + i];
    if (t < 16) { s_es[t] = 0.0f; s_ed[t] = 0.0f; }
    __syncthreads();
    int r = t >> 4, j4 = t & 15;
    const float4* sw4 = (const float4*)sw;
    float4 a = make_float4(0.f, 0.f, 0.f, 0.f);
#pragma unroll
    for (int kk = 0; kk < 64; kk++) {
        float xv = sx[r][kk];
        float4 wv = sw4[kk * 16 + j4];
        a.x = fmaf(xv, wv.x, a.x);
        a.y = fmaf(xv, wv.y, a.y);
        a.z = fmaf(xv, wv.z, a.z);
        a.w = fmaf(xv, wv.w, a.w);
    }
    *(float4*)&g_h[(row0 + r) * 64 + j4 * 4] = a;
    float4 av = *(const float4*)&asrc[j4 * 4];
    float4 dv = *(const float4*)&adst[j4 * 4];
    atomicAdd(&s_es[r], a.x * av.x + a.y * av.y + a.z * av.z + a.w * av.w);
    atomicAdd(&s_ed[r], a.x * dv.x + a.y * dv.y + a.z * dv.z + a.w * dv.w);
    __syncthreads();
    if (t < 16) { g_es[row0 + t] = s_es[t]; g_ed[row0 + t] = s_ed[t]; }
}

// ---------------- K5: warp-per-dst GAT aggregation + ReLU + residual + LN1 -
__global__ void k5_gat_agg(const float* __restrict__ x, const float* __restrict__ b_gat,
                           const float* __restrict__ g1, const float* __restrict__ b1) {
    int warp = (blockIdx.x * blockDim.x + threadIdx.x) >> 5;
    int lane = threadIdx.x & 31;
    if (warp >= N_NODES) return;
    int node = warp;
    int deg = g_cnt[node];
    int off = g_off[node];
    float edst = g_ed[node];
    float self_sc = leaky02(g_es[node] + edst);

    // sweep 1: global max (incl. self loop)
    float m = self_sc;
    for (int e0 = 0; e0 < deg; e0 += 32) {
        int e = e0 + lane;
        float sc = -1e30f;
        if (e < deg) {
            int src = g_csrc[off + e];
            sc = leaky02(g_es[src] + edst);
        }
        m = fmaxf(m, sc);
    }
#pragma unroll
    for (int o = 16; o; o >>= 1) m = fmaxf(m, __shfl_xor_sync(0xffffffffu, m, o));

    // sweep 2: exp-sum + feature aggregation (lane owns features lane*2, lane*2+1)
    float p_self = __expf(self_sc - m);
    float s = p_self;
    float2 hself = *(const float2*)&g_h[node * 64 + lane * 2];
    float accx = p_self * hself.x;
    float accy = p_self * hself.y;
    for (int e0 = 0; e0 < deg; e0 += 32) {
        int e = e0 + lane;
        float p = 0.0f;
        int src = 0;
        if (e < deg) {
            src = g_csrc[off + e];
            p = __expf(leaky02(g_es[src] + edst) - m);
        }
        int cnt = deg - e0; if (cnt > 32) cnt = 32;
        for (int j = 0; j < cnt; j++) {
            int bs = __shfl_sync(0xffffffffu, src, j);
            float bp = __shfl_sync(0xffffffffu, p, j);
            float2 hv = *(const float2*)&g_h[bs * 64 + lane * 2];
            accx = fmaf(bp, hv.x, accx);
            accy = fmaf(bp, hv.y, accy);
            s += bp;
        }
    }
    float inv = 1.0f / (s + 1e-16f);
    float2 xv = *(const float2*)&x[node * 64 + lane * 2];
    float2 bg = *(const float2*)&b_gat[lane * 2];
    float v0 = xv.x + fmaxf(accx * inv + bg.x, 0.0f);
    float v1 = xv.y + fmaxf(accy * inv + bg.y, 0.0f);
    float sum = v0 + v1, sumsq = v0 * v0 + v1 * v1;
#pragma unroll
    for (int o = 16; o; o >>= 1) {
        sum   += __shfl_xor_sync(0xffffffffu, sum, o);
        sumsq += __shfl_xor_sync(0xffffffffu, sumsq, o);
    }
    float mu = sum * (1.0f / 64.0f);
    float var = sumsq * (1.0f / 64.0f) - mu * mu;
    float rstd = rsqrtf(var + 1e-5f);
    float2 gv = *(const float2*)&g1[lane * 2];
    float2 bv = *(const float2*)&b1[lane * 2];
    float2 o2;
    o2.x = (v0 - mu) * rstd * gv.x + bv.x;
    o2.y = (v1 - mu) * rstd * gv.y + bv.y;
    *(float2*)&g_x1[node * 64 + lane * 2] = o2;
}

// ---------------- fused QKV projection, 16 rows/block ----------------------
__global__ void k_qkv(const float* __restrict__ wq, const float* __restrict__ bq,
                      const float* __restrict__ wk, const float* __restrict__ bk,
                      const float* __restrict__ wv, const float* __restrict__ bv) {
    __shared__ float swq[4096], swk[4096], swv[4096];
    __shared__ float sx[16][64];
    int t = threadIdx.x;
    for (int i = t; i < 4096; i += 256) { swq[i] = wq[i]; swk[i] = wk[i]; swv[i] = wv[i]; }
    int row0 = blockIdx.x * 16;
    for (int i = t; i < 1024; i += 256) sx[i >> 6][i & 63] = g_x1[row0 * 64 + i];
    __syncthreads();
    int r = t >> 4, j4 = t & 15;
    const float4* wq4 = (const float4*)swq;
    const float4* wk4 = (const float4*)swk;
    const float4* wv4 = (const float4*)swv;
    float4 aq = make_float4(0.f, 0.f, 0.f, 0.f);
    float4 ak = aq, av = aq;
#pragma unroll
    for (int kk = 0; kk < 64; kk++) {
        float xv = sx[r][kk];
        float4 q = wq4[kk * 16 + j4];
        float4 k = wk4[kk * 16 + j4];
        float4 v = wv4[kk * 16 + j4];
        aq.x = fmaf(xv, q.x, aq.x); aq.y = fmaf(xv, q.y, aq.y);
        aq.z = fmaf(xv, q.z, aq.z); aq.w = fmaf(xv, q.w, aq.w);
        ak.x = fmaf(xv, k.x, ak.x); ak.y = fmaf(xv, k.y, ak.y);
        ak.z = fmaf(xv, k.z, ak.z); ak.w = fmaf(xv, k.w, ak.w);
        av.x = fmaf(xv, v.x, av.x); av.y = fmaf(xv, v.y, av.y);
        av.z = fmaf(xv, v.z, av.z); av.w = fmaf(xv, v.w, av.w);
    }
    float4 bqv = *(const float4*)&bq[j4 * 4];
    float4 bkv = *(const float4*)&bk[j4 * 4];
    float4 bvv = *(const float4*)&bv[j4 * 4];
    aq.x += bqv.x; aq.y += bqv.y; aq.z += bqv.z; aq.w += bqv.w;
    ak.x += bkv.x; ak.y += bkv.y; ak.z += bkv.z; ak.w += bkv.w;
    av.x += bvv.x; av.y += bvv.y; av.z += bvv.z; av.w += bvv.w;
    int o = (row0 + r) * 64 + j4 * 4;
    *(float4*)&g_q[o] = aq;
    *(float4*)&g_k[o] = ak;
    *(float4*)&g_v[o] = av;
}

// ---------------- K6: dense attention, QT=2 queries per thread -------------
// grid = B*HEADS*2, 128 threads. Each block: (b,h), 256 queries.
#define KTILE 32
__global__ void __launch_bounds__(128) k6_attn() {
    __shared__ float sKt[8][512];       // d-major
    __shared__ float4 sV4[512][2];      // key-major 32B rows
    int bh = blockIdx.x >> 1;
    int half = blockIdx.x & 1;
    int b = bh >> 3, h = bh & 7;
    int base = b * NPG;
    int t = threadIdx.x;
    for (int i = t; i < 4096; i += 128) {
        int n = i >> 3, d = i & 7;
        sKt[d][n] = g_k[(base + n) * 64 + h * DH + d];
    }
    for (int i = t; i < 1024; i += 128) {
        int n = i >> 1, p = i & 1;
        sV4[n][p] = *(const float4*)&g_v[(base + n) * 64 + h * DH + p * 4];
    }
    __syncthreads();

    int q0 = half * 256 + t;
    int q1 = q0 + 128;
    const float scale = 0.3535533905932738f;   // 1/sqrt(8)
    u64 qq0[8], qq1[8];
    {
        const float* p0 = &g_q[(base + q0) * 64 + h * DH];
        const float* p1 = &g_q[(base + q1) * 64 + h * DH];
#pragma unroll
        for (int d = 0; d < 8; d++) {
            float a = p0[d] * scale; qq0[d] = f2pack(a, a);
            float c = p1[d] * scale; qq1[d] = f2pack(c, c);
        }
    }

    float m0 = -1e30f, m1 = -1e30f;
    u64 sum0 = 0ULL, sum1 = 0ULL;
    u64 a0[4] = {0ULL, 0ULL, 0ULL, 0ULL};
    u64 a1[4] = {0ULL, 0ULL, 0ULL, 0ULL};

#pragma unroll 1
    for (int tile = 0; tile < NPG / KTILE; tile++) {
        u64 sc0[KTILE / 2], sc1[KTILE / 2];
        float tm0 = -1e30f, tm1 = -1e30f;
#pragma unroll
        for (int j = 0; j < KTILE / 2; j++) {
            u64 s0 = 0ULL, s1 = 0ULL;
#pragma unroll
            for (int d = 0; d < 8; d++) {
                u64 kv = *(const u64*)&sKt[d][tile * KTILE + 2 * j];
                s0 = fma2(qq0[d], kv, s0);
                s1 = fma2(qq1[d], kv, s1);
            }
            sc0[j] = s0; sc1[j] = s1;
            float x0, x1, y0, y1;
            f2unpack(s0, x0, x1); tm0 = fmaxf(tm0, fmaxf(x0, x1));
            f2unpack(s1, y0, y1); tm1 = fmaxf(tm1, fmaxf(y0, y1));
        }
        float mn0 = fmaxf(m0, tm0), mn1 = fmaxf(m1, tm1);
        float r0 = __expf(m0 - mn0), r1 = __expf(m1 - mn1);
        m0 = mn0; m1 = mn1;
        u64 rr0 = f2pack(r0, r0), rr1 = f2pack(r1, r1);
        sum0 = mul2(sum0, rr0); sum1 = mul2(sum1, rr1);
#pragma unroll
        for (int p = 0; p < 4; p++) { a0[p] = mul2(a0[p], rr0); a1[p] = mul2(a1[p], rr1); }
#pragma unroll
        for (int j = 0; j < KTILE / 2; j++) {
            int k0 = tile * KTILE + 2 * j;
            const u64* v0 = (const u64*)&sV4[k0][0];
            const u64* v1 = (const u64*)&sV4[k0 + 1][0];
            float x0, x1; f2unpack(sc0[j], x0, x1);
            float p00 = __expf(x0 - m0);
            float p01 = __expf(x1 - m0);
            sum0 = add2(sum0, f2pack(p00, p01));
            u64 pa = f2pack(p00, p00), pb = f2pack(p01, p01);
#pragma unroll
            for (int p = 0; p < 4; p++) a0[p] = fma2(pa, v0[p], a0[p]);
#pragma unroll
            for (int p = 0; p < 4; p++) a0[p] = fma2(pb, v1[p], a0[p]);
            float y0, y1; f2unpack(sc1[j], y0, y1);
            float p10 = __expf(y0 - m1);
            float p11 = __expf(y1 - m1);
            sum1 = add2(sum1, f2pack(p10, p11));
            u64 pc = f2pack(p10, p10), pd = f2pack(p11, p11);
#pragma unroll
            for (int p = 0; p < 4; p++) a1[p] = fma2(pc, v0[p], a1[p]);
#pragma unroll
            for (int p = 0; p < 4; p++) a1[p] = fma2(pd, v1[p], a1[p]);
        }
    }
    {
        float sl, sh; f2unpack(sum0, sl, sh);
        float inv = 1.0f / (sl + sh);
        float o[8];
#pragma unroll
        for (int p = 0; p < 4; p++) f2unpack(a0[p], o[2 * p], o[2 * p + 1]);
        float* op = &g_ao[(base + q0) * 64 + h * DH];
        float4 oa = make_float4(o[0] * inv, o[1] * inv, o[2] * inv, o[3] * inv);
        float4 ob = make_float4(o[4] * inv, o[5] * inv, o[6] * inv, o[7] * inv);
        *(float4*)&op[0] = oa; *(float4*)&op[4] = ob;
    }
    {
        float sl, sh; f2unpack(sum1, sl, sh);
        float inv = 1.0f / (sl + sh);
        float o[8];
#pragma unroll
        for (int p = 0; p < 4; p++) f2unpack(a1[p], o[2 * p], o[2 * p + 1]);
        float* op = &g_ao[(base + q1) * 64 + h * DH];
        float4 oa = make_float4(o[0] * inv, o[1] * inv, o[2] * inv, o[3] * inv);
        float4 ob = make_float4(o[4] * inv, o[5] * inv, o[6] * inv, o[7] * inv);
        *(float4*)&op[0] = oa; *(float4*)&op[4] = ob;
    }
}

// ---------------- K7: out = LN(x1 + relu(ao @ wo + bo)) --------------------
__global__ void k7_out(const float* __restrict__ wo, const float* __restrict__ bo,
                       const float* __restrict__ g2, const float* __restrict__ b2,
                       float* __restrict__ out) {
    __shared__ float sw[4096];
    __shared__ float sx[16][64];
    __shared__ float red[16][2];
    int t = threadIdx.x;
    for (int i = t; i < 4096; i += 256) sw[i] = wo[i];
    int row0 = blockIdx.x * 16;
    for (int i = t; i < 1024; i += 256) sx[i >> 6][i & 63] = g_ao[row0 * 64 + i];
    if (t < 32) ((float*)red)[t] = 0.0f;
    __syncthreads();
    int r = t >> 4, j4 = t & 15;
    const float4* sw4 = (const float4*)sw;
    float4 a = make_float4(0.f, 0.f, 0.f, 0.f);
#pragma unroll
    for (int kk = 0; kk < 64; kk++) {
        float xv = sx[r][kk];
        float4 wv = sw4[kk * 16 + j4];
        a.x = fmaf(xv, wv.x, a.x);
        a.y = fmaf(xv, wv.y, a.y);
        a.z = fmaf(xv, wv.z, a.z);
        a.w = fmaf(xv, wv.w, a.w);
    }
    float4 bv = *(const float4*)&bo[j4 * 4];
    a.x = fmaxf(a.x + bv.x, 0.0f);
    a.y = fmaxf(a.y + bv.y, 0.0f);
    a.z = fmaxf(a.z + bv.z, 0.0f);
    a.w = fmaxf(a.w + bv.w, 0.0f);
    float4 x1v = *(const float4*)&g_x1[(row0 + r) * 64 + j4 * 4];
    float4 val = make_float4(x1v.x + a.x, x1v.y + a.y, x1v.z + a.z, x1v.w + a.w);
    float vsum = val.x + val.y + val.z + val.w;
    float vsq  = val.x * val.x + val.y * val.y + val.z * val.z + val.w * val.w;
    atomicAdd(&red[r][0], vsum);
    atomicAdd(&red[r][1], vsq);
    __syncthreads();
    float mu = red[r][0] * (1.0f / 64.0f);
    float var = red[r][1] * (1.0f / 64.0f) - mu * mu;
    float rstd = rsqrtf(var + 1e-5f);
    float4 gv = *(const float4*)&g2[j4 * 4];
    float4 bb = *(const float4*)&b2[j4 * 4];
    float4 ov;
    ov.x = (val.x - mu) * rstd * gv.x + bb.x;
    ov.y = (val.y - mu) * rstd * gv.y + bb.y;
    ov.z = (val.z - mu) * rstd * gv.z + bb.z;
    ov.w = (val.w - mu) * rstd * gv.w + bb.w;
    *(float4*)&out[(row0 + r) * 64 + j4 * 4] = ov;
}

// ---------------- launch ----------------------------------------------------
extern "C" void kernel_launch(void* const* d_in, const int* in_sizes, int n_in,
                              void* d_out, int out_size) {
    const float* x       = (const float*)d_in[0];
    const float* w_gat   = (const float*)d_in[1];
    const float* att_src = (const float*)d_in[2];
    const float* att_dst = (const float*)d_in[3];
    const float* b_gat   = (const float*)d_in[4];
    const float* g1      = (const float*)d_in[5];
    const float* b1      = (const float*)d_in[6];
    const float* wq      = (const float*)d_in[7];
    const float* bq      = (const float*)d_in[8];
    const float* wk      = (const float*)d_in[9];
    const float* bk      = (const float*)d_in[10];
    const float* wv      = (const float*)d_in[11];
    const float* bv      = (const float*)d_in[12];
    const float* wo      = (const float*)d_in[13];
    const float* bo      = (const float*)d_in[14];
    const float* g2      = (const float*)d_in[15];
    const float* b2      = (const float*)d_in[16];
    const int*   ei      = (const int*)d_in[17];
    float* out = (float*)d_out;

    kc_zero<<<N_NODES / 256, 256>>>();
    kc_count<<<E_EDGES / 256, 256>>>(ei);
    kc_scan<<<1, 1024>>>();
    kc_scatter<<<E_EDGES / 256, 256>>>(ei);
    k1_gat_proj<<<N_NODES / 16, 256>>>(x, w_gat, att_src, att_dst);
    k5_gat_agg<<<N_NODES * 32 / 256, 256>>>(x, b_gat, g1, b1);
    k_qkv<<<N_NODES / 16, 256>>>(wq, bq, wk, bk, wv, bv);
    k6_attn<<<B * HEADS * 2, 128>>>();
    k7_out<<<N_NODES / 16, 256>>>(wo, bo, g2, b2, out);
}